// round 14
// baseline (speedup 1.0000x reference)
#include <cuda_runtime.h>
#include <cstdint>

#define BB 16
#define NPTS 2048
#define MM 16
#define SS 128
#define NSPLIT 4
#define NCHUNK (NPTS / NSPLIT)        // 512 n per CTA
#define TX 64                          // threads in n direction
#define TY 4                           // threads in s direction
#define NCNT (NCHUNK / TX)             // 8 n per thread
#define NPAIR (NCNT / 2)               // 4 packed pairs
#define SCNT (SS / TY)                 // 32 s per thread
#define SPAD 257                       // padded float row stride
#define K2_SORT_BLOCKS ((BB * NPTS) / 128)   // 256 (128 n per block, i split 2-way)
#define K2_CM_BLOCKS BB                      // 16 (one per batch)
#define K2_TOTAL (K2_SORT_BLOCKS + K2_CM_BLOCKS)

static __device__ float g_d1T[BB * MM * NPTS];             // [b][m][n] min-over-s
static __device__ float g_partmin[BB * MM * NSPLIT * SS];  // per (bm,chunk), per-s min-over-chunk
static __device__ float g_part1[K2_SORT_BLOCKS];           // pcl_to_prim partials
static __device__ float g_part2[BB];                       // per-b prim_to_pcl partials
static __device__ unsigned g_ticket = 0;                   // last-block election counter

// ---- packed f32x2 helpers (add/mul/fma only — no packed min on sm_103a) ----
#define ADD2(d, a, b)    asm("add.rn.f32x2 %0, %1, %2;" : "=l"(d) : "l"(a), "l"(b))
#define FMA2(d, a, b, c) asm("fma.rn.f32x2 %0, %1, %2, %3;" : "=l"(d) : "l"(a), "l"(b), "l"(c))
#define PACK2(d, lo, hi) asm("mov.b64 %0, {%1, %2};" : "=l"(d) \
                             : "r"(__float_as_uint(lo)), "r"(__float_as_uint(hi)))
#define UNPACK2(lo, hi, s) do { unsigned _ul, _uh;                                  \
    asm("mov.b64 {%0, %1}, %2;" : "=r"(_ul), "=r"(_uh) : "l"(s));                   \
    (lo) = __uint_as_float(_ul); (hi) = __uint_as_float(_uh); } while (0)

// Shuffle-based block sum over 256 threads (1 sync). Result valid on tid 0.
__device__ __forceinline__ float block_sum256(float v, float* sw8) {
    const int tid = threadIdx.x;
    const int lane = tid & 31;
    const int w = tid >> 5;
#pragma unroll
    for (int off = 16; off > 0; off >>= 1)
        v += __shfl_down_sync(0xffffffffu, v, off);
    if (lane == 0) sw8[w] = v;
    __syncthreads();
    float r = 0.0f;
    if (w == 0) {
        r = (lane < 8) ? sw8[lane] : 0.0f;
#pragma unroll
        for (int off = 4; off > 0; off >>= 1)
            r += __shfl_down_sync(0xffffffffu, r, off);
    }
    return r;
}

// ---------------------------------------------------------------------------
// Kernel 1 (R11-proven, unchanged): one CTA per (b, m, n-chunk). Self-staging
// pcl slice into smem; packed-f32x2 hot loop; dual epilogue.
// ---------------------------------------------------------------------------
__global__ __launch_bounds__(TX * TY, 3) void k1(const float* __restrict__ pcl,
                                                 const float* __restrict__ prim) {
    const int bid = blockIdx.x;            // = bm * NSPLIT + chunk
    const int chunk = bid & (NSPLIT - 1);
    const int bm = bid >> 2;
    const int b = bm >> 4;
    const int m = bm & 15;
    const int tid = threadIdx.x;
    const int x = tid & (TX - 1);
    const int y = tid >> 6;                // 0..3

    __shared__ ulonglong2 sAC[SS];         // {(a,a),(c,c)}   2KB
    __shared__ ulonglong2 sDQ[SS];         // {(d,d),(q,q)}   2KB
    __shared__ float sminS[SCNT * SPAD];   // [k][tid], padded rows  ~33KB
    __shared__ float sred[TY * NCHUNK];    // dmin combine / pcl stage  8KB

    // ---- stage prim (s-side) ----
    const float* pp = prim + (size_t)(b * MM + m) * SS * 3;
    for (int s = tid; s < SS; s += TX * TY) {
        float a = pp[3 * s + 0];
        float c = pp[3 * s + 1];
        float d = pp[3 * s + 2];
        float q = a * a + c * c + d * d;
        unsigned long long aa, cc, dd, qq;
        PACK2(aa, a, a); PACK2(cc, c, c); PACK2(dd, d, d); PACK2(qq, q, q);
        sAC[s] = make_ulonglong2(aa, cc);
        sDQ[s] = make_ulonglong2(dd, qq);
    }

    // ---- stage pcl slice (n-side) into sred: spcl[nl*3 + c] ----
    {
        const float* src = pcl + ((size_t)(b * NPTS + chunk * NCHUNK)) * (MM * 3) + m * 3;
        float* spcl = sred;
#pragma unroll
        for (int kk = 0; kk < 6; kk++) {
            int j = tid + kk * 256;        // 0..1535
            int n = j / 3;
            int c = j - 3 * n;
            spcl[j] = src[n * 48 + c];
        }
    }
    __syncthreads();

    // ---- build packed registers from smem ----
    const float* spcl = sred;
    unsigned long long nx2[NPAIR], ny2[NPAIR], nz2[NPAIR], uu2[NPAIR];
    float dmin[NCNT];
#pragma unroll
    for (int p = 0; p < NPAIR; p++) {
        int na = ((2 * p) * TX + x) * 3;
        int nb = ((2 * p + 1) * TX + x) * 3;
        float xa = spcl[na], ya = spcl[na + 1], za = spcl[na + 2];
        float xb = spcl[nb], yb = spcl[nb + 1], zb = spcl[nb + 2];
        PACK2(nx2[p], -2.0f * xa, -2.0f * xb);
        PACK2(ny2[p], -2.0f * ya, -2.0f * yb);
        PACK2(nz2[p], -2.0f * za, -2.0f * zb);
        PACK2(uu2[p], xa * xa + ya * ya + za * za,
                      xb * xb + yb * yb + zb * zb);
        dmin[2 * p] = 3.4e38f;
        dmin[2 * p + 1] = 3.4e38f;
    }
    __syncthreads();   // everyone done reading spcl before sred is rewritten

    // ---- hot loop: 32 s x 8 n per thread ----
#pragma unroll
    for (int k = 0; k < SCNT; k++) {
        const int s = y * SCNT + k;
        ulonglong2 ac = sAC[s];
        ulonglong2 dq = sDQ[s];
        float pm[NPAIR];
#pragma unroll
        for (int p = 0; p < NPAIR; p++) {
            unsigned long long t;
            ADD2(t, dq.y, uu2[p]);             // q + |x|^2
            FMA2(t, ac.x, nx2[p], t);          // -2 a x
            FMA2(t, ac.y, ny2[p], t);
            FMA2(t, dq.x, nz2[p], t);
            float f0, f1;
            UNPACK2(f0, f1, t);
            dmin[2 * p]     = fminf(dmin[2 * p], f0);
            dmin[2 * p + 1] = fminf(dmin[2 * p + 1], f1);
            pm[p] = fminf(f0, f1);
        }
        sminS[k * SPAD + tid] =
            fminf(fminf(pm[0], pm[1]), fminf(pm[2], pm[3]));
    }

    // ---- epilogue 1: dmin — combine the 4 y-slices via smem ----
#pragma unroll
    for (int j = 0; j < NCNT; j++) sred[y * NCHUNK + j * TX + x] = dmin[j];
    __syncthreads();

    float* d1out = g_d1T + (size_t)bm * NPTS + chunk * NCHUNK;
#pragma unroll
    for (int r = 0; r < 2; r++) {
        int nl = r * 256 + tid;
        float v = fminf(fminf(sred[0 * NCHUNK + nl], sred[1 * NCHUNK + nl]),
                        fminf(sred[2 * NCHUNK + nl], sred[3 * NCHUNK + nl]));
        d1out[nl] = v;
    }

    // ---- epilogue 2: smin — per s, min over its 64 contributing threads ----
    if (tid < SS) {
        const int kk = tid & 31;
        const int yy = tid >> 5;
        const float* rowp = sminS + kk * SPAD + 64 * yy;
        float v = rowp[0];
#pragma unroll
        for (int i = 1; i < 64; i++) v = fminf(v, rowp[i]);
        g_partmin[(size_t)bid * SS + tid] = v;
    }
}

// ---------------------------------------------------------------------------
// Kernel 2:
//  blocks [0,256): sort-free stick-breaking, i-loop split 2-way: block handles
//    128 n; thread t = (n_local = t&127, half = t>>7) computes weights for
//    i in [half*8, half*8+8). 2x warps vs R13 -> latency hiding.
//  blocks [256,272): one per batch b — colmean + areas + per-b partial.
//  LAST block (fence + atomic ticket): sum 256 + 16 scalars, write outputs.
// ---------------------------------------------------------------------------
__global__ __launch_bounds__(256) void k2(const float* __restrict__ probs,
                                          const float* __restrict__ size_,
                                          float* __restrict__ out, int out_size) {
    __shared__ float sw8[8];
    __shared__ float cm[MM];
    __shared__ float areas[MM];
    __shared__ int is_last;

    const int tid = threadIdx.x;
    const int lane = tid & 31;
    const int w = tid >> 5;

    if (blockIdx.x < K2_SORT_BLOCKS) {
        const int nidx = blockIdx.x * 128 + (tid & 127);  // < B*N
        const int half = tid >> 7;                        // 0 or 1
        const int b = nidx >> 11;
        const int n = nidx & (NPTS - 1);

        float d[MM], p[MM], q[MM];
#pragma unroll
        for (int i = 0; i < MM; i++)
            d[i] = g_d1T[(size_t)(b * MM + i) * NPTS + n];
#pragma unroll
        for (int i = 0; i < MM; i++) {
            p[i] = probs[b * MM + i];
            q[i] = 1.0f - p[i];
        }

        // weight_i = p_i * prod_{j before i in stable sort} (1-p_j)
        // this thread covers i in [half*8, half*8+8)
        float sum = 0.0f;
#pragma unroll
        for (int ii = 0; ii < MM / 2; ii++) {
            const int i = half * (MM / 2) + ii;
            float wgt = d[i] * p[i];
#pragma unroll
            for (int j = 0; j < MM; j++) {
                if (j == i) continue;
                bool before = (j < i) ? (d[j] <= d[i]) : (d[j] < d[i]);
                wgt *= before ? q[j] : 1.0f;
            }
            sum += wgt;
        }

        float tot = block_sum256(sum, sw8);
        if (tid == 0) g_part1[blockIdx.x] = tot;
    } else {
        const int b = blockIdx.x - K2_SORT_BLOCKS;       // 0..15

        // ---- colmean for this b: warp w handles m = 2w, 2w+1 ----
#pragma unroll
        for (int t = 0; t < 2; t++) {
            const int m = w * 2 + t;
            const float* pm = g_partmin + (size_t)(b * MM + m) * NSPLIT * SS;
            float sum = 0.0f;
#pragma unroll
            for (int i = 0; i < SS / 32; i++) {
                int s = lane + 32 * i;
                float mn = fminf(fminf(pm[0 * SS + s], pm[1 * SS + s]),
                                 fminf(pm[2 * SS + s], pm[3 * SS + s]));
                if (mn >= 1e30f) mn = 0.0f;   // INF_CLAMP rule
                sum += mn;
            }
#pragma unroll
            for (int off = 16; off > 0; off >>= 1)
                sum += __shfl_down_sync(0xffffffffu, sum, off);
            if (lane == 0) cm[m] = sum * (1.0f / SS);
        }

        // ---- areas (threads 0-15; sizes in [0.05,1] -> fast pow safe) ----
        if (tid < MM) {
            const float FOUR_PI = 12.566370614359172f;
            float s0 = size_[(b * MM + tid) * 3 + 0];
            float s1 = size_[(b * MM + tid) * 3 + 1];
            float s2 = size_[(b * MM + tid) * 3 + 2];
            float inner = (__powf(s0 * s1, 1.6f) + __powf(s0 * s2, 1.6f) +
                           __powf(s1 * s2, 1.6f)) * (1.0f / 3.0f);
            areas[tid] = FOUR_PI * __powf(inner, 0.625f);
        }
        __syncthreads();

        // ---- per-b normalization + partial (warp 0) ----
        if (w == 0) {
            float contrib = 0.0f;
            if (lane < MM) {
                float sb = 0.0f;
#pragma unroll
                for (int j = 0; j < MM; j++) sb += areas[j];
                contrib = cm[lane] * probs[b * MM + lane] *
                          ((float)MM * areas[lane] / sb) * (1.0f / (BB * MM));
            }
#pragma unroll
            for (int off = 16; off > 0; off >>= 1)
                contrib += __shfl_down_sync(0xffffffffu, contrib, off);
            if (lane == 0) g_part2[b] = contrib;
        }
    }

    // ---- last-block election: tiny final combine ----
    __threadfence();
    if (tid == 0) {
        unsigned t = atomicAdd(&g_ticket, 1u);
        is_last = (t == K2_TOTAL - 1);
    }
    __syncthreads();
    if (!is_last) return;

    float v1 = (tid < K2_SORT_BLOCKS) ? g_part1[tid] : 0.0f;
    float p1 = block_sum256(v1, sw8);          // valid on tid 0
    __syncthreads();                            // sw8 reuse
    float v2 = (tid < BB) ? g_part2[tid] : 0.0f;
    float p2 = block_sum256(v2, sw8);

    if (tid == 0) {
        float pcl_to_prim = p1 * (1.0f / ((float)BB * (float)NPTS));
        float prim_to_pcl = p2;
        float total = pcl_to_prim + prim_to_pcl;
        if (out_size > 0) out[0] = total;
        if (out_size > 1) out[1] = pcl_to_prim;
        if (out_size > 2) out[2] = prim_to_pcl;
        if (out_size > 3) out[3] = 0.0f;
        g_ticket = 0;   // reset for the next graph replay
    }
}

extern "C" void kernel_launch(void* const* d_in, const int* in_sizes, int n_in,
                              void* d_out, int out_size) {
    const float* pcl   = (const float*)d_in[0];  // (B, N, M, 3)
    const float* prim  = (const float*)d_in[1];  // (B, M, S, 3)
    const float* size_ = (const float*)d_in[2];  // (B, M, 3)
    const float* probs = (const float*)d_in[3];  // (B, M)

    k1<<<BB * MM * NSPLIT, TX * TY>>>(pcl, prim);
    k2<<<K2_TOTAL, 256>>>(probs, size_, (float*)d_out, out_size);
}

// round 15
// speedup vs baseline: 1.0849x; 1.0849x over previous
#include <cuda_runtime.h>
#include <cstdint>

#define BB 16
#define NPTS 2048
#define MM 16
#define SS 128
#define NSPLIT 4
#define NCHUNK (NPTS / NSPLIT)        // 512 n per CTA
#define TX 64                          // threads in n direction
#define TY 4                           // threads in s direction
#define NCNT (NCHUNK / TX)             // 8 n per thread
#define NPAIR (NCNT / 2)               // 4 packed pairs
#define SCNT (SS / TY)                 // 32 s per thread
#define SPAD 257                       // padded float row stride
#define K2_SORT_BLOCKS ((BB * NPTS) / 256)   // 128
#define K2_CM_BLOCKS BB                      // 16 (one per batch)
#define K2_TOTAL (K2_SORT_BLOCKS + K2_CM_BLOCKS)

static __device__ float g_d1T[BB * MM * NPTS];             // [b][m][n] min-over-s
static __device__ float g_partmin[BB * MM * NSPLIT * SS];  // per (bm,chunk), per-s min-over-chunk
static __device__ float g_part1[K2_SORT_BLOCKS];           // pcl_to_prim partials
static __device__ float g_part2[BB];                       // per-b prim_to_pcl partials
static __device__ unsigned g_ticket = 0;                   // last-block election counter

// ---- packed f32x2 helpers (add/mul/fma only — no packed min on sm_103a) ----
#define ADD2(d, a, b)    asm("add.rn.f32x2 %0, %1, %2;" : "=l"(d) : "l"(a), "l"(b))
#define FMA2(d, a, b, c) asm("fma.rn.f32x2 %0, %1, %2, %3;" : "=l"(d) : "l"(a), "l"(b), "l"(c))
#define PACK2(d, lo, hi) asm("mov.b64 %0, {%1, %2};" : "=l"(d) \
                             : "r"(__float_as_uint(lo)), "r"(__float_as_uint(hi)))
#define UNPACK2(lo, hi, s) do { unsigned _ul, _uh;                                  \
    asm("mov.b64 {%0, %1}, %2;" : "=r"(_ul), "=r"(_uh) : "l"(s));                   \
    (lo) = __uint_as_float(_ul); (hi) = __uint_as_float(_uh); } while (0)

// Shuffle-based block sum over 256 threads (1 sync). Result valid on tid 0.
__device__ __forceinline__ float block_sum256(float v, float* sw8) {
    const int tid = threadIdx.x;
    const int lane = tid & 31;
    const int w = tid >> 5;
#pragma unroll
    for (int off = 16; off > 0; off >>= 1)
        v += __shfl_down_sync(0xffffffffu, v, off);
    if (lane == 0) sw8[w] = v;
    __syncthreads();
    float r = 0.0f;
    if (w == 0) {
        r = (lane < 8) ? sw8[lane] : 0.0f;
#pragma unroll
        for (int off = 4; off > 0; off >>= 1)
            r += __shfl_down_sync(0xffffffffu, r, off);
    }
    return r;
}

// ---------------------------------------------------------------------------
// Kernel 1: one CTA per (b, m, n-chunk). Self-staging pcl slice into smem;
// packed-f32x2 hot loop; dual epilogue. NOW __launch_bounds__(256,4):
// smem (45KB) allows 5 CTAs/SM; forcing 64 regs gives 4 CTAs/SM = 8 warps
// per scheduler (vs 6) and cuts the wave count 2.31 -> 1.73.
// ---------------------------------------------------------------------------
__global__ __launch_bounds__(TX * TY, 4) void k1(const float* __restrict__ pcl,
                                                 const float* __restrict__ prim) {
    const int bid = blockIdx.x;            // = bm * NSPLIT + chunk
    const int chunk = bid & (NSPLIT - 1);
    const int bm = bid >> 2;
    const int b = bm >> 4;
    const int m = bm & 15;
    const int tid = threadIdx.x;
    const int x = tid & (TX - 1);
    const int y = tid >> 6;                // 0..3

    __shared__ ulonglong2 sAC[SS];         // {(a,a),(c,c)}   2KB
    __shared__ ulonglong2 sDQ[SS];         // {(d,d),(q,q)}   2KB
    __shared__ float sminS[SCNT * SPAD];   // [k][tid], padded rows  ~33KB
    __shared__ float sred[TY * NCHUNK];    // dmin combine / pcl stage  8KB

    // ---- stage prim (s-side) ----
    const float* pp = prim + (size_t)(b * MM + m) * SS * 3;
    for (int s = tid; s < SS; s += TX * TY) {
        float a = pp[3 * s + 0];
        float c = pp[3 * s + 1];
        float d = pp[3 * s + 2];
        float q = a * a + c * c + d * d;
        unsigned long long aa, cc, dd, qq;
        PACK2(aa, a, a); PACK2(cc, c, c); PACK2(dd, d, d); PACK2(qq, q, q);
        sAC[s] = make_ulonglong2(aa, cc);
        sDQ[s] = make_ulonglong2(dd, qq);
    }

    // ---- stage pcl slice (n-side) into sred: spcl[nl*3 + c] ----
    {
        const float* src = pcl + ((size_t)(b * NPTS + chunk * NCHUNK)) * (MM * 3) + m * 3;
        float* spcl = sred;
#pragma unroll
        for (int kk = 0; kk < 6; kk++) {
            int j = tid + kk * 256;        // 0..1535
            int n = j / 3;
            int c = j - 3 * n;
            spcl[j] = src[n * 48 + c];
        }
    }
    __syncthreads();

    // ---- build packed registers from smem ----
    const float* spcl = sred;
    unsigned long long nx2[NPAIR], ny2[NPAIR], nz2[NPAIR], uu2[NPAIR];
    float dmin[NCNT];
#pragma unroll
    for (int p = 0; p < NPAIR; p++) {
        int na = ((2 * p) * TX + x) * 3;
        int nb = ((2 * p + 1) * TX + x) * 3;
        float xa = spcl[na], ya = spcl[na + 1], za = spcl[na + 2];
        float xb = spcl[nb], yb = spcl[nb + 1], zb = spcl[nb + 2];
        PACK2(nx2[p], -2.0f * xa, -2.0f * xb);
        PACK2(ny2[p], -2.0f * ya, -2.0f * yb);
        PACK2(nz2[p], -2.0f * za, -2.0f * zb);
        PACK2(uu2[p], xa * xa + ya * ya + za * za,
                      xb * xb + yb * yb + zb * zb);
        dmin[2 * p] = 3.4e38f;
        dmin[2 * p + 1] = 3.4e38f;
    }
    __syncthreads();   // everyone done reading spcl before sred is rewritten

    // ---- hot loop: 32 s x 8 n per thread ----
#pragma unroll
    for (int k = 0; k < SCNT; k++) {
        const int s = y * SCNT + k;
        ulonglong2 ac = sAC[s];
        ulonglong2 dq = sDQ[s];
        float pm[NPAIR];
#pragma unroll
        for (int p = 0; p < NPAIR; p++) {
            unsigned long long t;
            ADD2(t, dq.y, uu2[p]);             // q + |x|^2
            FMA2(t, ac.x, nx2[p], t);          // -2 a x
            FMA2(t, ac.y, ny2[p], t);
            FMA2(t, dq.x, nz2[p], t);
            float f0, f1;
            UNPACK2(f0, f1, t);
            dmin[2 * p]     = fminf(dmin[2 * p], f0);
            dmin[2 * p + 1] = fminf(dmin[2 * p + 1], f1);
            pm[p] = fminf(f0, f1);
        }
        sminS[k * SPAD + tid] =
            fminf(fminf(pm[0], pm[1]), fminf(pm[2], pm[3]));
    }

    // ---- epilogue 1: dmin — combine the 4 y-slices via smem ----
#pragma unroll
    for (int j = 0; j < NCNT; j++) sred[y * NCHUNK + j * TX + x] = dmin[j];
    __syncthreads();

    float* d1out = g_d1T + (size_t)bm * NPTS + chunk * NCHUNK;
#pragma unroll
    for (int r = 0; r < 2; r++) {
        int nl = r * 256 + tid;
        float v = fminf(fminf(sred[0 * NCHUNK + nl], sred[1 * NCHUNK + nl]),
                        fminf(sred[2 * NCHUNK + nl], sred[3 * NCHUNK + nl]));
        d1out[nl] = v;
    }

    // ---- epilogue 2: smin — per s, min over its 64 contributing threads ----
    if (tid < SS) {
        const int kk = tid & 31;
        const int yy = tid >> 5;
        const float* rowp = sminS + kk * SPAD + 64 * yy;
        float v = rowp[0];
#pragma unroll
        for (int i = 1; i < 64; i++) v = fminf(v, rowp[i]);
        g_partmin[(size_t)bid * SS + tid] = v;
    }
}

// ---------------------------------------------------------------------------
// Kernel 2 (R13-proven form, reverted):
//  blocks [0,128): per (b,n) sort-free stick-breaking (full 16-i loop per
//    thread); shuffle block-sum -> g_part1.
//  blocks [128,144): one per batch b — colmean + areas + per-b partial.
//  LAST block (fence + atomic ticket): sum 128 + 16 scalars, write outputs.
// ---------------------------------------------------------------------------
__global__ __launch_bounds__(256) void k2(const float* __restrict__ probs,
                                          const float* __restrict__ size_,
                                          float* __restrict__ out, int out_size) {
    __shared__ float sw8[8];
    __shared__ float cm[MM];
    __shared__ float areas[MM];
    __shared__ int is_last;

    const int tid = threadIdx.x;
    const int lane = tid & 31;
    const int w = tid >> 5;

    if (blockIdx.x < K2_SORT_BLOCKS) {
        const int idx = blockIdx.x * 256 + tid;          // < B*N
        const int b = idx >> 11;
        const int n = idx & (NPTS - 1);

        float d[MM], p[MM], q[MM];
#pragma unroll
        for (int i = 0; i < MM; i++)
            d[i] = g_d1T[(size_t)(b * MM + i) * NPTS + n];
#pragma unroll
        for (int i = 0; i < MM; i++) {
            p[i] = probs[b * MM + i];
            q[i] = 1.0f - p[i];
        }

        // weight_i = p_i * prod_{j before i in stable sort} (1-p_j)
        float sum = 0.0f;
#pragma unroll
        for (int i = 0; i < MM; i++) {
            float wgt = d[i] * p[i];
#pragma unroll
            for (int j = 0; j < MM; j++) {
                if (j == i) continue;
                bool before = (j < i) ? (d[j] <= d[i]) : (d[j] < d[i]);
                wgt *= before ? q[j] : 1.0f;
            }
            sum += wgt;
        }

        float tot = block_sum256(sum, sw8);
        if (tid == 0) g_part1[blockIdx.x] = tot;
    } else {
        const int b = blockIdx.x - K2_SORT_BLOCKS;       // 0..15

        // ---- colmean for this b: warp w handles m = 2w, 2w+1 ----
#pragma unroll
        for (int t = 0; t < 2; t++) {
            const int m = w * 2 + t;
            const float* pm = g_partmin + (size_t)(b * MM + m) * NSPLIT * SS;
            float sum = 0.0f;
#pragma unroll
            for (int i = 0; i < SS / 32; i++) {
                int s = lane + 32 * i;
                float mn = fminf(fminf(pm[0 * SS + s], pm[1 * SS + s]),
                                 fminf(pm[2 * SS + s], pm[3 * SS + s]));
                if (mn >= 1e30f) mn = 0.0f;   // INF_CLAMP rule
                sum += mn;
            }
#pragma unroll
            for (int off = 16; off > 0; off >>= 1)
                sum += __shfl_down_sync(0xffffffffu, sum, off);
            if (lane == 0) cm[m] = sum * (1.0f / SS);
        }

        // ---- areas (threads 0-15; sizes in [0.05,1] -> fast pow safe) ----
        if (tid < MM) {
            const float FOUR_PI = 12.566370614359172f;
            float s0 = size_[(b * MM + tid) * 3 + 0];
            float s1 = size_[(b * MM + tid) * 3 + 1];
            float s2 = size_[(b * MM + tid) * 3 + 2];
            float inner = (__powf(s0 * s1, 1.6f) + __powf(s0 * s2, 1.6f) +
                           __powf(s1 * s2, 1.6f)) * (1.0f / 3.0f);
            areas[tid] = FOUR_PI * __powf(inner, 0.625f);
        }
        __syncthreads();

        // ---- per-b normalization + partial (warp 0) ----
        if (w == 0) {
            float contrib = 0.0f;
            if (lane < MM) {
                float sb = 0.0f;
#pragma unroll
                for (int j = 0; j < MM; j++) sb += areas[j];
                contrib = cm[lane] * probs[b * MM + lane] *
                          ((float)MM * areas[lane] / sb) * (1.0f / (BB * MM));
            }
#pragma unroll
            for (int off = 16; off > 0; off >>= 1)
                contrib += __shfl_down_sync(0xffffffffu, contrib, off);
            if (lane == 0) g_part2[b] = contrib;
        }
    }

    // ---- last-block election: tiny final combine ----
    __threadfence();
    if (tid == 0) {
        unsigned t = atomicAdd(&g_ticket, 1u);
        is_last = (t == K2_TOTAL - 1);
    }
    __syncthreads();
    if (!is_last) return;

    float v1 = (tid < K2_SORT_BLOCKS) ? g_part1[tid] : 0.0f;
    float p1 = block_sum256(v1, sw8);          // valid on tid 0
    __syncthreads();                            // sw8 reuse
    float v2 = (tid < BB) ? g_part2[tid] : 0.0f;
    float p2 = block_sum256(v2, sw8);

    if (tid == 0) {
        float pcl_to_prim = p1 * (1.0f / ((float)BB * (float)NPTS));
        float prim_to_pcl = p2;
        float total = pcl_to_prim + prim_to_pcl;
        if (out_size > 0) out[0] = total;
        if (out_size > 1) out[1] = pcl_to_prim;
        if (out_size > 2) out[2] = prim_to_pcl;
        if (out_size > 3) out[3] = 0.0f;
        g_ticket = 0;   // reset for the next graph replay
    }
}

extern "C" void kernel_launch(void* const* d_in, const int* in_sizes, int n_in,
                              void* d_out, int out_size) {
    const float* pcl   = (const float*)d_in[0];  // (B, N, M, 3)
    const float* prim  = (const float*)d_in[1];  // (B, M, S, 3)
    const float* size_ = (const float*)d_in[2];  // (B, M, 3)
    const float* probs = (const float*)d_in[3];  // (B, M)

    k1<<<BB * MM * NSPLIT, TX * TY>>>(pcl, prim);
    k2<<<K2_TOTAL, 256>>>(probs, size_, (float*)d_out, out_size);
}